// round 13
// baseline (speedup 1.0000x reference)
#include <cuda_runtime.h>
#include <cuda_bf16.h>
#include <cuda_fp16.h>
#include <math.h>

// ---------------- problem constants ----------------
#define NMAX 10000
#define EMAX 320000
#define MMAX (EMAX + NMAX)   // edges + self loops

// ---------------- device scratch ----------------
__device__ __align__(16) float g_H0 [NMAX * 512];
__device__ __align__(16) float g_H0A[NMAX * 512];
__device__ __align__(16) float g_H1 [NMAX * 128];
__device__ __align__(16) float g_AS0[NMAX * 4];
__device__ __align__(16) float g_AD0[NMAX * 4];
__device__ __align__(16) float g_AS1[NMAX];
__device__ __align__(16) float g_AD1[NMAX];
__device__ __align__(16) float g_S1 [NMAX];
__device__ __align__(16) float g_S2 [NMAX];
__device__ __align__(16) float g_V  [260];              // v1[128], v2[128], c
__device__ __align__(16) unsigned g_H0h[NMAX * 256];    // H0 as packed half2
__device__ __align__(16) unsigned g_H1h[NMAX * 64];     // H1 as packed half2
__device__ __align__(16) int   g_deg[NMAX];
__device__ __align__(16) int   g_off[NMAX + 1];
__device__ __align__(16) int   g_cur[NMAX];
__device__ __align__(16) int   g_srt[MMAX];

// buffer ids
#define B_H0   0
#define B_H0A  1
#define B_H1   2
#define B_AS0  5
#define B_AD0  6
#define B_AS1  7
#define B_AD1  8
#define B_S1   9
#define B_S2   10
#define B_V    11
#define B_EXT  (-1)

// half-copy ids
#define H_NONE (-1)
#define H_H0h  0
#define H_H1h  1

__device__ __forceinline__ float* buf_sel(int id) {
    switch (id) {
        case B_H0:  return g_H0;
        case B_H0A: return g_H0A;
        case B_H1:  return g_H1;
        case B_AS0: return g_AS0;
        case B_AD0: return g_AD0;
        case B_AS1: return g_AS1;
        case B_AD1: return g_AD1;
        case B_S1:  return g_S1;
        case B_V:   return g_V;
        default:    return g_S2;
    }
}

__device__ __forceinline__ unsigned* hbuf_sel(int id) {
    return (id == H_H0h) ? g_H0h : g_H1h;
}

// ---------------- CSR build kernels ----------------
__global__ void zero_deg_kernel(int n) {
    int i = blockIdx.x * blockDim.x + threadIdx.x;
    if (i < n) g_deg[i] = 0;
}

__global__ void hist_kernel(const int* __restrict__ ei, int E, int n) {
    int e = blockIdx.x * blockDim.x + threadIdx.x;
    int M = E + n;
    if (e >= M) return;
    int dst = (e < E) ? ei[E + e] : (e - E);
    if ((unsigned)dst < (unsigned)n)
        atomicAdd(&g_deg[dst], 1);
}

__global__ void scan_kernel(int n) {
    __shared__ int sm[1024];
    int t = threadIdx.x;
    int chunk = (n + 1023) >> 10;
    int b = t * chunk;
    int e = min(n, b + chunk);
    int s = 0;
    for (int i = b; i < e; i++) s += g_deg[i];
    sm[t] = s;
    __syncthreads();
    for (int o = 1; o < 1024; o <<= 1) {
        int v = (t >= o) ? sm[t - o] : 0;
        __syncthreads();
        sm[t] += v;
        __syncthreads();
    }
    int run = sm[t] - s;
    for (int i = b; i < e; i++) {
        g_off[i] = run;
        g_cur[i] = run;
        run += g_deg[i];
    }
    if (t == 1023) g_off[n] = sm[1023];
}

__global__ void scatter_kernel(const int* __restrict__ ei, int E, int n) {
    int e = blockIdx.x * blockDim.x + threadIdx.x;
    int M = E + n;
    if (e >= M) return;
    int src, dst;
    if (e < E) { src = ei[e]; dst = ei[E + e]; }
    else       { src = e - E; dst = e - E; }
    if ((unsigned)dst >= (unsigned)n || (unsigned)src >= (unsigned)n) return;
    int pos = atomicAdd(&g_cur[dst], 1);
    if (pos < MMAX) g_srt[pos] = src;
}

// ---------------- v-vectors: v1 = Wout^T w1, v2 = Wout^T w2, c = bout.(w1+w2) ----------------
__global__ void vec_kernel(const float* __restrict__ Wout, const float* __restrict__ bout,
                           const float* __restrict__ Wedge) {
    int k = threadIdx.x;   // 128
    float a1 = 0.f, a2 = 0.f;
    for (int j = 0; j < 128; j++) {
        float wo = Wout[j * 128 + k];
        a1 += wo * Wedge[j];
        a2 += wo * Wedge[128 + j];
    }
    g_V[k] = a1;
    g_V[128 + k] = a2;
    if (k == 0) {
        float c = 0.f;
        for (int j = 0; j < 128; j++) c += bout[j] * (Wedge[j] + Wedge[128 + j]);
        g_V[256] = c;
    }
}

// ---------------- bf16x3 TC GEMM, software-pipelined double buffer ----------------
#define TBM 128
#define TBN 64
#define TBK 32
#define KP  (TBK / 2)
#define SSTR (KP + 4)     // 20
#define A_SZ (TBM * SSTR)
#define B_SZ (TBN * SSTR)
#define GSMEM_BYTES (2 * (A_SZ + A_SZ + B_SZ + B_SZ) * 4)  // 61440

__device__ __forceinline__ unsigned pack_bf2(float a, float b) {
    __nv_bfloat162 p = __floats2bfloat162_rn(a, b);
    return *reinterpret_cast<unsigned*>(&p);
}

__device__ __forceinline__ void mma_bf16(float acc[4], unsigned a0, unsigned a1,
                                         unsigned a2, unsigned a3,
                                         unsigned b0, unsigned b1) {
    asm volatile(
        "mma.sync.aligned.m16n8k16.row.col.f32.bf16.bf16.f32 "
        "{%0,%1,%2,%3}, {%4,%5,%6,%7}, {%8,%9}, {%0,%1,%2,%3};"
        : "+f"(acc[0]), "+f"(acc[1]), "+f"(acc[2]), "+f"(acc[3])
        : "r"(a0), "r"(a1), "r"(a2), "r"(a3), "r"(b0), "r"(b1));
}

__global__ void __launch_bounds__(256)
gemm_tc_kernel(const float* __restrict__ Aext, int aid,
               const float* __restrict__ B,
               const float* __restrict__ bias,
               int cid, int c2id, int M, int N, int K) {
    const float* A = (aid == B_EXT) ? Aext : buf_sel(aid);
    float* C = buf_sel(cid);
    unsigned* C2 = (c2id >= 0) ? hbuf_sel(c2id) : nullptr;
    int N2 = N >> 1;

    extern __shared__ unsigned smu[];
    unsigned* AsH = smu;
    unsigned* AsL = AsH + 2 * A_SZ;
    unsigned* BsH = AsL + 2 * A_SZ;
    unsigned* BsL = BsH + 2 * B_SZ;

    int tid = threadIdx.x;
    int warp = tid >> 5, lane = tid & 31;
    int wm = warp >> 2;
    int wn = warp & 3;
    int bm = blockIdx.y * TBM;
    int bn = blockIdx.x * TBN;

    int lr = tid >> 3;
    int lc = tid & 7;

    float acc[4][2][4];
#pragma unroll
    for (int mt = 0; mt < 4; mt++)
#pragma unroll
        for (int nt = 0; nt < 2; nt++)
#pragma unroll
            for (int r = 0; r < 4; r++) acc[mt][nt][r] = 0.f;

    int qrow = lane >> 2;
    int qcol = lane & 3;

    float4 ra[4], rb[2];

    auto load_tile = [&](int k0) {
#pragma unroll
        for (int i = 0; i < 4; i++) {
            int rg = bm + lr + 32 * i;
            ra[i] = make_float4(0.f, 0.f, 0.f, 0.f);
            if (rg < M) ra[i] = *(const float4*)&A[(size_t)rg * K + k0 + lc * 4];
        }
#pragma unroll
        for (int i = 0; i < 2; i++)
            rb[i] = *(const float4*)&B[(size_t)(bn + lr + 32 * i) * K + k0 + lc * 4];
    };

    auto cvt_store = [&](int buf) {
        unsigned* aH = AsH + buf * A_SZ;
        unsigned* aL = AsL + buf * A_SZ;
        unsigned* bH = BsH + buf * B_SZ;
        unsigned* bL = BsL + buf * B_SZ;
#pragma unroll
        for (int i = 0; i < 4; i++) {
            float4 v = ra[i];
            float hx = __bfloat162float(__float2bfloat16_rn(v.x));
            float hy = __bfloat162float(__float2bfloat16_rn(v.y));
            float hz = __bfloat162float(__float2bfloat16_rn(v.z));
            float hw = __bfloat162float(__float2bfloat16_rn(v.w));
            int rl = lr + 32 * i;
            unsigned* dH = &aH[rl * SSTR + lc * 2];
            unsigned* dL = &aL[rl * SSTR + lc * 2];
            dH[0] = pack_bf2(hx, hy);
            dH[1] = pack_bf2(hz, hw);
            dL[0] = pack_bf2(v.x - hx, v.y - hy);
            dL[1] = pack_bf2(v.z - hz, v.w - hw);
        }
#pragma unroll
        for (int i = 0; i < 2; i++) {
            float4 v = rb[i];
            float hx = __bfloat162float(__float2bfloat16_rn(v.x));
            float hy = __bfloat162float(__float2bfloat16_rn(v.y));
            float hz = __bfloat162float(__float2bfloat16_rn(v.z));
            float hw = __bfloat162float(__float2bfloat16_rn(v.w));
            int rl = lr + 32 * i;
            unsigned* dH = &bH[rl * SSTR + lc * 2];
            unsigned* dL = &bL[rl * SSTR + lc * 2];
            dH[0] = pack_bf2(hx, hy);
            dH[1] = pack_bf2(hz, hw);
            dL[0] = pack_bf2(v.x - hx, v.y - hy);
            dL[1] = pack_bf2(v.z - hz, v.w - hw);
        }
    };

    int nTiles = K / TBK;

    load_tile(0);
    cvt_store(0);
    __syncthreads();

    for (int kt = 0; kt < nTiles; kt++) {
        int cur = kt & 1;
        if (kt + 1 < nTiles) load_tile((kt + 1) * TBK);

        unsigned* aH = AsH + cur * A_SZ;
        unsigned* aL = AsL + cur * A_SZ;
        unsigned* bH = BsH + cur * B_SZ;
        unsigned* bL = BsL + cur * B_SZ;

#pragma unroll
        for (int ks = 0; ks < TBK / 16; ks++) {
            int kb = ks * 8;
            unsigned bh[2][2], bl[2][2];
#pragma unroll
            for (int nt = 0; nt < 2; nt++) {
                int nn = wn * 16 + nt * 8 + qrow;
                bh[nt][0] = bH[nn * SSTR + kb + qcol];
                bh[nt][1] = bH[nn * SSTR + kb + qcol + 4];
                bl[nt][0] = bL[nn * SSTR + kb + qcol];
                bl[nt][1] = bL[nn * SSTR + kb + qcol + 4];
            }
#pragma unroll
            for (int mt = 0; mt < 4; mt++) {
                int mm = wm * 64 + mt * 16 + qrow;
                unsigned ah0 = aH[mm * SSTR + kb + qcol];
                unsigned ah1 = aH[(mm + 8) * SSTR + kb + qcol];
                unsigned ah2 = aH[mm * SSTR + kb + qcol + 4];
                unsigned ah3 = aH[(mm + 8) * SSTR + kb + qcol + 4];
                unsigned al0 = aL[mm * SSTR + kb + qcol];
                unsigned al1 = aL[(mm + 8) * SSTR + kb + qcol];
                unsigned al2 = aL[mm * SSTR + kb + qcol + 4];
                unsigned al3 = aL[(mm + 8) * SSTR + kb + qcol + 4];
#pragma unroll
                for (int nt = 0; nt < 2; nt++) {
                    mma_bf16(acc[mt][nt], ah0, ah1, ah2, ah3, bh[nt][0], bh[nt][1]);
                    mma_bf16(acc[mt][nt], ah0, ah1, ah2, ah3, bl[nt][0], bl[nt][1]);
                    mma_bf16(acc[mt][nt], al0, al1, al2, al3, bh[nt][0], bh[nt][1]);
                }
            }
        }

        if (kt + 1 < nTiles) cvt_store((kt + 1) & 1);
        __syncthreads();
    }

    // epilogue: fp32 C + optional packed-half C2
#pragma unroll
    for (int mt = 0; mt < 4; mt++) {
#pragma unroll
        for (int nt = 0; nt < 2; nt++) {
            int row = bm + wm * 64 + mt * 16 + qrow;
            int col = bn + wn * 16 + nt * 8 + qcol * 2;
            float b0 = 0.f, b1 = 0.f;
            if (bias) { b0 = bias[col]; b1 = bias[col + 1]; }
            if (row < M) {
                float2 o = {acc[mt][nt][0] + b0, acc[mt][nt][1] + b1};
                *(float2*)&C[(size_t)row * N + col] = o;
                if (C2) {
                    __half2 h = __floats2half2_rn(o.x, o.y);
                    C2[(size_t)row * N2 + (col >> 1)] = *reinterpret_cast<unsigned*>(&h);
                }
            }
            if (row + 8 < M) {
                float2 o = {acc[mt][nt][2] + b0, acc[mt][nt][3] + b1};
                *(float2*)&C[(size_t)(row + 8) * N + col] = o;
                if (C2) {
                    __half2 h = __floats2half2_rn(o.x, o.y);
                    C2[(size_t)(row + 8) * N2 + (col >> 1)] = *reinterpret_cast<unsigned*>(&h);
                }
            }
        }
    }
}

// ---------------- attention coefficients ----------------
__global__ void attn_coef_kernel(int hid, const float* __restrict__ atts_ext,
                                 const float* __restrict__ attd_ext,
                                 int osid, int odid, int heads) {
    const float* H = buf_sel(hid);
    const float* atts = atts_ext;
    const float* attd = attd_ext;
    float* osrc = buf_sel(osid);
    float* odst = buf_sel(odid);

    int node = blockIdx.x;
    int t = threadIdx.x;            // 128
    int w = t >> 5, lane = t & 31;
    int Ct = heads * 128;
    float ps[4] = {0.f, 0.f, 0.f, 0.f}, pd[4] = {0.f, 0.f, 0.f, 0.f};
    for (int k = 0; k < heads; k++) {
        float h = H[(size_t)node * Ct + k * 128 + t];
        ps[k] = h * atts[k * 128 + t];
        pd[k] = h * attd[k * 128 + t];
    }
#pragma unroll
    for (int o = 16; o; o >>= 1) {
#pragma unroll
        for (int k = 0; k < 4; k++) {
            ps[k] += __shfl_xor_sync(~0u, ps[k], o);
            pd[k] += __shfl_xor_sync(~0u, pd[k], o);
        }
    }
    __shared__ float ss[4][4], sd[4][4];
    if (lane == 0) {
#pragma unroll
        for (int k = 0; k < 4; k++) { ss[w][k] = ps[k]; sd[w][k] = pd[k]; }
    }
    __syncthreads();
    if (t < heads) {
        osrc[node * heads + t] = ss[0][t] + ss[1][t] + ss[2][t] + ss[3][t];
        odst[node * heads + t] = sd[0][t] + sd[1][t] + sd[2][t] + sd[3][t];
    }
}

// ---------------- layer-0 aggregation: fp16 gather ----------------
__global__ void agg0_kernel(const float* __restrict__ b0) {
    int node = blockIdx.x;
    int t = threadIdx.x;            // 128
    int w = t >> 5;
    int beg = g_off[node], end = g_off[node + 1];

    float adsth = g_AD0[node * 4 + w];

    float4 acc = {0.f, 0.f, 0.f, 0.f};
    float denom = 0.f;
#pragma unroll 2
    for (int i = beg; i < end; i++) {
        int s = g_srt[i];
        float a = g_AS0[s * 4 + w] + adsth;
        a = (a >= 0.f) ? a : 0.2f * a;
        float ex = __expf(a);
        denom += ex;
        uint2 v = *(const uint2*)&g_H0h[(size_t)s * 256 + t * 2];
        float2 p0 = __half22float2(*reinterpret_cast<__half2*>(&v.x));
        float2 p1 = __half22float2(*reinterpret_cast<__half2*>(&v.y));
        acc.x += ex * p0.x; acc.y += ex * p0.y;
        acc.z += ex * p1.x; acc.w += ex * p1.y;
    }
    float inv = 1.f / (denom + 1e-16f);
    float4 bb = *(const float4*)&b0[t * 4];
    float4 o4;
    o4.x = acc.x * inv + bb.x;
    o4.y = acc.y * inv + bb.y;
    o4.z = acc.z * inv + bb.z;
    o4.w = acc.w * inv + bb.w;
    o4.x = (o4.x > 0.f) ? o4.x : expm1f(o4.x);
    o4.y = (o4.y > 0.f) ? o4.y : expm1f(o4.y);
    o4.z = (o4.z > 0.f) ? o4.z : expm1f(o4.z);
    o4.w = (o4.w > 0.f) ? o4.w : expm1f(o4.w);
    *(float4*)&g_H0A[(size_t)node * 512 + t * 4] = o4;
}

// ---------------- layer-1 aggregation, fused with edge-score dots ----------------
// Computes h1a = elu(agg + b1), then S1[node]=h1a.v1, S2[node]=h1a.v2 in-register.
__global__ void agg1_kernel(const float* __restrict__ b1, int n) {
    int w = threadIdx.x >> 5, lane = threadIdx.x & 31;
    int node = blockIdx.x * 4 + w;
    if (node >= n) return;
    int beg = g_off[node], end = g_off[node + 1];
    float adv = g_AD1[node];

    float4 acc = {0.f, 0.f, 0.f, 0.f};
    float denom = 0.f;
#pragma unroll 2
    for (int i = beg; i < end; i++) {
        int s = g_srt[i];
        float a = g_AS1[s] + adv;
        a = (a >= 0.f) ? a : 0.2f * a;
        float ex = __expf(a);
        denom += ex;
        uint2 v = *(const uint2*)&g_H1h[(size_t)s * 64 + lane * 2];
        float2 p0 = __half22float2(*reinterpret_cast<__half2*>(&v.x));
        float2 p1 = __half22float2(*reinterpret_cast<__half2*>(&v.y));
        acc.x += ex * p0.x; acc.y += ex * p0.y;
        acc.z += ex * p1.x; acc.w += ex * p1.y;
    }
    float inv = 1.f / (denom + 1e-16f);
    float4 bb = *(const float4*)&b1[lane * 4];
    float4 o4;
    o4.x = acc.x * inv + bb.x;
    o4.y = acc.y * inv + bb.y;
    o4.z = acc.z * inv + bb.z;
    o4.w = acc.w * inv + bb.w;
    o4.x = (o4.x > 0.f) ? o4.x : expm1f(o4.x);
    o4.y = (o4.y > 0.f) ? o4.y : expm1f(o4.y);
    o4.z = (o4.z > 0.f) ? o4.z : expm1f(o4.z);
    o4.w = (o4.w > 0.f) ? o4.w : expm1f(o4.w);

    // fused edge-score dots: s1 = h1a . v1, s2 = h1a . v2
    float4 v1 = *(const float4*)&g_V[lane * 4];
    float4 v2 = *(const float4*)&g_V[128 + lane * 4];
    float d1 = o4.x * v1.x + o4.y * v1.y + o4.z * v1.z + o4.w * v1.w;
    float d2 = o4.x * v2.x + o4.y * v2.y + o4.z * v2.z + o4.w * v2.w;
#pragma unroll
    for (int o = 16; o; o >>= 1) {
        d1 += __shfl_xor_sync(~0u, d1, o);
        d2 += __shfl_xor_sync(~0u, d2, o);
    }
    if (lane == 0) {
        g_S1[node] = d1;
        g_S2[node] = d2;
    }
}

// ---------------- final outer sum: out[i*n+j] = s1[i] + s2[j] + c + bedge ----------------
__global__ void outer_kernel(const float* __restrict__ bedge, float* __restrict__ out, int n) {
    int i = blockIdx.x;
    float v = g_S1[i] + bedge[0] + g_V[256];
    float* row = out + (size_t)i * n;
    int n4 = n >> 2;
    const float4* s24 = (const float4*)g_S2;
    for (int j = threadIdx.x; j < n4; j += blockDim.x) {
        float4 b = s24[j];
        float4 o = {v + b.x, v + b.y, v + b.z, v + b.w};
        __stcs(&((float4*)row)[j], o);
    }
    for (int j = (n4 << 2) + threadIdx.x; j < n; j += blockDim.x)
        row[j] = v + g_S2[j];
}

// ---------------- host launcher ----------------
extern "C" void kernel_launch(void* const* d_in, const int* in_sizes, int n_in,
                              void* d_out, int out_size) {
    const float* x        = (const float*)d_in[0];
    const int*   ei       = (const int*)d_in[1];     // int32
    const float* W0       = (const float*)d_in[2];
    const float* att_src0 = (const float*)d_in[3];
    const float* att_dst0 = (const float*)d_in[4];
    const float* b0       = (const float*)d_in[5];
    const float* W1       = (const float*)d_in[6];
    const float* att_src1 = (const float*)d_in[7];
    const float* att_dst1 = (const float*)d_in[8];
    const float* b1       = (const float*)d_in[9];
    const float* Wout     = (const float*)d_in[10];
    const float* bout     = (const float*)d_in[11];
    const float* Wedge    = (const float*)d_in[12];
    const float* bedge    = (const float*)d_in[13];
    float* out = (float*)d_out;

    int n = in_sizes[0] / 128;
    int E = in_sizes[1] / 2;
    int M = E + n;

    cudaFuncSetAttribute(gemm_tc_kernel,
                         cudaFuncAttributeMaxDynamicSharedMemorySize, GSMEM_BYTES);

    // Side stream: CSR chain feeds agg0 (evJoin right after scatter);
    // vec_kernel joins before agg1 (its consumer via the fused dot).
    cudaStream_t side;
    cudaStreamCreateWithFlags(&side, cudaStreamNonBlocking);
    cudaEvent_t evFork, evJoin, evJoin2;
    cudaEventCreateWithFlags(&evFork, cudaEventDisableTiming);
    cudaEventCreateWithFlags(&evJoin, cudaEventDisableTiming);
    cudaEventCreateWithFlags(&evJoin2, cudaEventDisableTiming);

    cudaEventRecord(evFork, (cudaStream_t)0);
    cudaStreamWaitEvent(side, evFork, 0);

    zero_deg_kernel<<<(n + 255) / 256, 256, 0, side>>>(n);
    hist_kernel<<<(M + 255) / 256, 256, 0, side>>>(ei, E, n);
    scan_kernel<<<1, 1024, 0, side>>>(n);
    scatter_kernel<<<(M + 255) / 256, 256, 0, side>>>(ei, E, n);
    cudaEventRecord(evJoin, side);
    vec_kernel<<<1, 128, 0, side>>>(Wout, bout, Wedge);
    cudaEventRecord(evJoin2, side);

    // ---- layer 0: H0 = x @ W0^T (bf16x3 TC, pipelined; also writes fp16 copy) ----
    {
        dim3 grid(512 / TBN, (n + TBM - 1) / TBM);
        gemm_tc_kernel<<<grid, 256, GSMEM_BYTES>>>(x, B_EXT, W0, nullptr, B_H0, H_H0h, n, 512, 128);
    }
    attn_coef_kernel<<<n, 128>>>(B_H0, att_src0, att_dst0, B_AS0, B_AD0, 4);

    cudaStreamWaitEvent((cudaStream_t)0, evJoin, 0);
    agg0_kernel<<<n, 128>>>(b0);

    // ---- layer 1: H1 = H0A @ W1^T (also writes fp16 copy) ----
    {
        dim3 grid(128 / TBN, (n + TBM - 1) / TBM);
        gemm_tc_kernel<<<grid, 256, GSMEM_BYTES>>>(nullptr, B_H0A, W1, nullptr, B_H1, H_H1h, n, 128, 512);
    }
    attn_coef_kernel<<<n, 128>>>(B_H1, att_src1, att_dst1, B_AS1, B_AD1, 1);

    // agg1 consumes g_V (fused edge-score dots) -> join vec first
    cudaStreamWaitEvent((cudaStream_t)0, evJoin2, 0);
    agg1_kernel<<<(n + 3) / 4, 128>>>(b1, n);

    // ---- final n x n outer sum ----
    outer_kernel<<<n, 512>>>(bedge, out, n);
}

// round 14
// speedup vs baseline: 1.0004x; 1.0004x over previous
#include <cuda_runtime.h>
#include <cuda_bf16.h>
#include <cuda_fp16.h>
#include <math.h>

// ---------------- problem constants ----------------
#define NMAX 10000
#define EMAX 320000
#define MMAX (EMAX + NMAX)   // edges + self loops

// ---------------- device scratch ----------------
__device__ __align__(16) float g_H0 [NMAX * 512];
__device__ __align__(16) float g_H0A[NMAX * 512];
__device__ __align__(16) float g_H1 [NMAX * 128];
__device__ __align__(16) float g_AS0[NMAX * 4];
__device__ __align__(16) float g_AD0[NMAX * 4];
__device__ __align__(16) float g_AS1[NMAX];
__device__ __align__(16) float g_AD1[NMAX];
__device__ __align__(16) float g_S1 [NMAX];
__device__ __align__(16) float g_S2 [NMAX];
__device__ __align__(16) float g_V  [260];              // v1[128], v2[128], c
__device__ __align__(16) unsigned g_H0h[NMAX * 256];    // H0 as packed half2
__device__ __align__(16) unsigned g_H1h[NMAX * 64];     // H1 as packed half2
__device__ __align__(16) int   g_deg[NMAX];
__device__ __align__(16) int   g_off[NMAX + 1];
__device__ __align__(16) int   g_cur[NMAX];
__device__ __align__(16) int   g_srt[MMAX];

// buffer ids
#define B_H0   0
#define B_H0A  1
#define B_H1   2
#define B_AS0  5
#define B_AD0  6
#define B_AS1  7
#define B_AD1  8
#define B_S1   9
#define B_S2   10
#define B_V    11
#define B_EXT  (-1)

// half-copy ids
#define H_NONE (-1)
#define H_H0h  0
#define H_H1h  1

__device__ __forceinline__ float* buf_sel(int id) {
    switch (id) {
        case B_H0:  return g_H0;
        case B_H0A: return g_H0A;
        case B_H1:  return g_H1;
        case B_AS0: return g_AS0;
        case B_AD0: return g_AD0;
        case B_AS1: return g_AS1;
        case B_AD1: return g_AD1;
        case B_S1:  return g_S1;
        case B_V:   return g_V;
        default:    return g_S2;
    }
}

__device__ __forceinline__ unsigned* hbuf_sel(int id) {
    return (id == H_H0h) ? g_H0h : g_H1h;
}

// ---------------- CSR build kernels ----------------
__global__ void zero_deg_kernel(int n) {
    int i = blockIdx.x * blockDim.x + threadIdx.x;
    if (i < n) g_deg[i] = 0;
}

__global__ void hist_kernel(const int* __restrict__ ei, int E, int n) {
    int e = blockIdx.x * blockDim.x + threadIdx.x;
    int M = E + n;
    if (e >= M) return;
    int dst = (e < E) ? ei[E + e] : (e - E);
    if ((unsigned)dst < (unsigned)n)
        atomicAdd(&g_deg[dst], 1);
}

__global__ void scan_kernel(int n) {
    __shared__ int sm[1024];
    int t = threadIdx.x;
    int chunk = (n + 1023) >> 10;
    int b = t * chunk;
    int e = min(n, b + chunk);
    int s = 0;
    for (int i = b; i < e; i++) s += g_deg[i];
    sm[t] = s;
    __syncthreads();
    for (int o = 1; o < 1024; o <<= 1) {
        int v = (t >= o) ? sm[t - o] : 0;
        __syncthreads();
        sm[t] += v;
        __syncthreads();
    }
    int run = sm[t] - s;
    for (int i = b; i < e; i++) {
        g_off[i] = run;
        g_cur[i] = run;
        run += g_deg[i];
    }
    if (t == 1023) g_off[n] = sm[1023];
}

__global__ void scatter_kernel(const int* __restrict__ ei, int E, int n) {
    int e = blockIdx.x * blockDim.x + threadIdx.x;
    int M = E + n;
    if (e >= M) return;
    int src, dst;
    if (e < E) { src = ei[e]; dst = ei[E + e]; }
    else       { src = e - E; dst = e - E; }
    if ((unsigned)dst >= (unsigned)n || (unsigned)src >= (unsigned)n) return;
    int pos = atomicAdd(&g_cur[dst], 1);
    if (pos < MMAX) g_srt[pos] = src;
}

// ---------------- v-vectors: v1 = Wout^T w1, v2 = Wout^T w2, c = bout.(w1+w2) ----------------
__global__ void vec_kernel(const float* __restrict__ Wout, const float* __restrict__ bout,
                           const float* __restrict__ Wedge) {
    int k = threadIdx.x;   // 128
    float a1 = 0.f, a2 = 0.f;
    for (int j = 0; j < 128; j++) {
        float wo = Wout[j * 128 + k];
        a1 += wo * Wedge[j];
        a2 += wo * Wedge[128 + j];
    }
    g_V[k] = a1;
    g_V[128 + k] = a2;
    if (k == 0) {
        float c = 0.f;
        for (int j = 0; j < 128; j++) c += bout[j] * (Wedge[j] + Wedge[128 + j]);
        g_V[256] = c;
    }
}

// ---------------- bf16x3 TC GEMM, software-pipelined double buffer ----------------
#define TBM 128
#define TBN 64
#define TBK 32
#define KP  (TBK / 2)
#define SSTR (KP + 4)     // 20
#define A_SZ (TBM * SSTR)
#define B_SZ (TBN * SSTR)
#define GSMEM_BYTES (2 * (A_SZ + A_SZ + B_SZ + B_SZ) * 4)  // 61440

__device__ __forceinline__ unsigned pack_bf2(float a, float b) {
    __nv_bfloat162 p = __floats2bfloat162_rn(a, b);
    return *reinterpret_cast<unsigned*>(&p);
}

__device__ __forceinline__ void mma_bf16(float acc[4], unsigned a0, unsigned a1,
                                         unsigned a2, unsigned a3,
                                         unsigned b0, unsigned b1) {
    asm volatile(
        "mma.sync.aligned.m16n8k16.row.col.f32.bf16.bf16.f32 "
        "{%0,%1,%2,%3}, {%4,%5,%6,%7}, {%8,%9}, {%0,%1,%2,%3};"
        : "+f"(acc[0]), "+f"(acc[1]), "+f"(acc[2]), "+f"(acc[3])
        : "r"(a0), "r"(a1), "r"(a2), "r"(a3), "r"(b0), "r"(b1));
}

__global__ void __launch_bounds__(256)
gemm_tc_kernel(const float* __restrict__ Aext, int aid,
               const float* __restrict__ B,
               const float* __restrict__ bias,
               int cid, int c2id, int M, int N, int K) {
    const float* A = (aid == B_EXT) ? Aext : buf_sel(aid);
    float* C = buf_sel(cid);
    unsigned* C2 = (c2id >= 0) ? hbuf_sel(c2id) : nullptr;
    int N2 = N >> 1;

    extern __shared__ unsigned smu[];
    unsigned* AsH = smu;
    unsigned* AsL = AsH + 2 * A_SZ;
    unsigned* BsH = AsL + 2 * A_SZ;
    unsigned* BsL = BsH + 2 * B_SZ;

    int tid = threadIdx.x;
    int warp = tid >> 5, lane = tid & 31;
    int wm = warp >> 2;
    int wn = warp & 3;
    int bm = blockIdx.y * TBM;
    int bn = blockIdx.x * TBN;

    int lr = tid >> 3;
    int lc = tid & 7;

    float acc[4][2][4];
#pragma unroll
    for (int mt = 0; mt < 4; mt++)
#pragma unroll
        for (int nt = 0; nt < 2; nt++)
#pragma unroll
            for (int r = 0; r < 4; r++) acc[mt][nt][r] = 0.f;

    int qrow = lane >> 2;
    int qcol = lane & 3;

    float4 ra[4], rb[2];

    auto load_tile = [&](int k0) {
#pragma unroll
        for (int i = 0; i < 4; i++) {
            int rg = bm + lr + 32 * i;
            ra[i] = make_float4(0.f, 0.f, 0.f, 0.f);
            if (rg < M) ra[i] = *(const float4*)&A[(size_t)rg * K + k0 + lc * 4];
        }
#pragma unroll
        for (int i = 0; i < 2; i++)
            rb[i] = *(const float4*)&B[(size_t)(bn + lr + 32 * i) * K + k0 + lc * 4];
    };

    auto cvt_store = [&](int buf) {
        unsigned* aH = AsH + buf * A_SZ;
        unsigned* aL = AsL + buf * A_SZ;
        unsigned* bH = BsH + buf * B_SZ;
        unsigned* bL = BsL + buf * B_SZ;
#pragma unroll
        for (int i = 0; i < 4; i++) {
            float4 v = ra[i];
            float hx = __bfloat162float(__float2bfloat16_rn(v.x));
            float hy = __bfloat162float(__float2bfloat16_rn(v.y));
            float hz = __bfloat162float(__float2bfloat16_rn(v.z));
            float hw = __bfloat162float(__float2bfloat16_rn(v.w));
            int rl = lr + 32 * i;
            unsigned* dH = &aH[rl * SSTR + lc * 2];
            unsigned* dL = &aL[rl * SSTR + lc * 2];
            dH[0] = pack_bf2(hx, hy);
            dH[1] = pack_bf2(hz, hw);
            dL[0] = pack_bf2(v.x - hx, v.y - hy);
            dL[1] = pack_bf2(v.z - hz, v.w - hw);
        }
#pragma unroll
        for (int i = 0; i < 2; i++) {
            float4 v = rb[i];
            float hx = __bfloat162float(__float2bfloat16_rn(v.x));
            float hy = __bfloat162float(__float2bfloat16_rn(v.y));
            float hz = __bfloat162float(__float2bfloat16_rn(v.z));
            float hw = __bfloat162float(__float2bfloat16_rn(v.w));
            int rl = lr + 32 * i;
            unsigned* dH = &bH[rl * SSTR + lc * 2];
            unsigned* dL = &bL[rl * SSTR + lc * 2];
            dH[0] = pack_bf2(hx, hy);
            dH[1] = pack_bf2(hz, hw);
            dL[0] = pack_bf2(v.x - hx, v.y - hy);
            dL[1] = pack_bf2(v.z - hz, v.w - hw);
        }
    };

    int nTiles = K / TBK;

    load_tile(0);
    cvt_store(0);
    __syncthreads();

    for (int kt = 0; kt < nTiles; kt++) {
        int cur = kt & 1;
        if (kt + 1 < nTiles) load_tile((kt + 1) * TBK);

        unsigned* aH = AsH + cur * A_SZ;
        unsigned* aL = AsL + cur * A_SZ;
        unsigned* bH = BsH + cur * B_SZ;
        unsigned* bL = BsL + cur * B_SZ;

#pragma unroll
        for (int ks = 0; ks < TBK / 16; ks++) {
            int kb = ks * 8;
            unsigned bh[2][2], bl[2][2];
#pragma unroll
            for (int nt = 0; nt < 2; nt++) {
                int nn = wn * 16 + nt * 8 + qrow;
                bh[nt][0] = bH[nn * SSTR + kb + qcol];
                bh[nt][1] = bH[nn * SSTR + kb + qcol + 4];
                bl[nt][0] = bL[nn * SSTR + kb + qcol];
                bl[nt][1] = bL[nn * SSTR + kb + qcol + 4];
            }
#pragma unroll
            for (int mt = 0; mt < 4; mt++) {
                int mm = wm * 64 + mt * 16 + qrow;
                unsigned ah0 = aH[mm * SSTR + kb + qcol];
                unsigned ah1 = aH[(mm + 8) * SSTR + kb + qcol];
                unsigned ah2 = aH[mm * SSTR + kb + qcol + 4];
                unsigned ah3 = aH[(mm + 8) * SSTR + kb + qcol + 4];
                unsigned al0 = aL[mm * SSTR + kb + qcol];
                unsigned al1 = aL[(mm + 8) * SSTR + kb + qcol];
                unsigned al2 = aL[mm * SSTR + kb + qcol + 4];
                unsigned al3 = aL[(mm + 8) * SSTR + kb + qcol + 4];
#pragma unroll
                for (int nt = 0; nt < 2; nt++) {
                    mma_bf16(acc[mt][nt], ah0, ah1, ah2, ah3, bh[nt][0], bh[nt][1]);
                    mma_bf16(acc[mt][nt], ah0, ah1, ah2, ah3, bl[nt][0], bl[nt][1]);
                    mma_bf16(acc[mt][nt], al0, al1, al2, al3, bh[nt][0], bh[nt][1]);
                }
            }
        }

        if (kt + 1 < nTiles) cvt_store((kt + 1) & 1);
        __syncthreads();
    }

    // epilogue: fp32 C + optional packed-half C2
#pragma unroll
    for (int mt = 0; mt < 4; mt++) {
#pragma unroll
        for (int nt = 0; nt < 2; nt++) {
            int row = bm + wm * 64 + mt * 16 + qrow;
            int col = bn + wn * 16 + nt * 8 + qcol * 2;
            float b0 = 0.f, b1 = 0.f;
            if (bias) { b0 = bias[col]; b1 = bias[col + 1]; }
            if (row < M) {
                float2 o = {acc[mt][nt][0] + b0, acc[mt][nt][1] + b1};
                *(float2*)&C[(size_t)row * N + col] = o;
                if (C2) {
                    __half2 h = __floats2half2_rn(o.x, o.y);
                    C2[(size_t)row * N2 + (col >> 1)] = *reinterpret_cast<unsigned*>(&h);
                }
            }
            if (row + 8 < M) {
                float2 o = {acc[mt][nt][2] + b0, acc[mt][nt][3] + b1};
                *(float2*)&C[(size_t)(row + 8) * N + col] = o;
                if (C2) {
                    __half2 h = __floats2half2_rn(o.x, o.y);
                    C2[(size_t)(row + 8) * N2 + (col >> 1)] = *reinterpret_cast<unsigned*>(&h);
                }
            }
        }
    }
}

// ---------------- attention coefficients ----------------
__global__ void attn_coef_kernel(int hid, const float* __restrict__ atts_ext,
                                 const float* __restrict__ attd_ext,
                                 int osid, int odid, int heads) {
    const float* H = buf_sel(hid);
    const float* atts = atts_ext;
    const float* attd = attd_ext;
    float* osrc = buf_sel(osid);
    float* odst = buf_sel(odid);

    int node = blockIdx.x;
    int t = threadIdx.x;            // 128
    int w = t >> 5, lane = t & 31;
    int Ct = heads * 128;
    float ps[4] = {0.f, 0.f, 0.f, 0.f}, pd[4] = {0.f, 0.f, 0.f, 0.f};
    for (int k = 0; k < heads; k++) {
        float h = H[(size_t)node * Ct + k * 128 + t];
        ps[k] = h * atts[k * 128 + t];
        pd[k] = h * attd[k * 128 + t];
    }
#pragma unroll
    for (int o = 16; o; o >>= 1) {
#pragma unroll
        for (int k = 0; k < 4; k++) {
            ps[k] += __shfl_xor_sync(~0u, ps[k], o);
            pd[k] += __shfl_xor_sync(~0u, pd[k], o);
        }
    }
    __shared__ float ss[4][4], sd[4][4];
    if (lane == 0) {
#pragma unroll
        for (int k = 0; k < 4; k++) { ss[w][k] = ps[k]; sd[w][k] = pd[k]; }
    }
    __syncthreads();
    if (t < heads) {
        osrc[node * heads + t] = ss[0][t] + ss[1][t] + ss[2][t] + ss[3][t];
        odst[node * heads + t] = sd[0][t] + sd[1][t] + sd[2][t] + sd[3][t];
    }
}

// ---------------- layer-0 aggregation: fp16 gather ----------------
__global__ void agg0_kernel(const float* __restrict__ b0) {
    int node = blockIdx.x;
    int t = threadIdx.x;            // 128
    int w = t >> 5;
    int beg = g_off[node], end = g_off[node + 1];

    float adsth = g_AD0[node * 4 + w];

    float4 acc = {0.f, 0.f, 0.f, 0.f};
    float denom = 0.f;
#pragma unroll 2
    for (int i = beg; i < end; i++) {
        int s = g_srt[i];
        float a = g_AS0[s * 4 + w] + adsth;
        a = (a >= 0.f) ? a : 0.2f * a;
        float ex = __expf(a);
        denom += ex;
        uint2 v = *(const uint2*)&g_H0h[(size_t)s * 256 + t * 2];
        float2 p0 = __half22float2(*reinterpret_cast<__half2*>(&v.x));
        float2 p1 = __half22float2(*reinterpret_cast<__half2*>(&v.y));
        acc.x += ex * p0.x; acc.y += ex * p0.y;
        acc.z += ex * p1.x; acc.w += ex * p1.y;
    }
    float inv = 1.f / (denom + 1e-16f);
    float4 bb = *(const float4*)&b0[t * 4];
    float4 o4;
    o4.x = acc.x * inv + bb.x;
    o4.y = acc.y * inv + bb.y;
    o4.z = acc.z * inv + bb.z;
    o4.w = acc.w * inv + bb.w;
    o4.x = (o4.x > 0.f) ? o4.x : expm1f(o4.x);
    o4.y = (o4.y > 0.f) ? o4.y : expm1f(o4.y);
    o4.z = (o4.z > 0.f) ? o4.z : expm1f(o4.z);
    o4.w = (o4.w > 0.f) ? o4.w : expm1f(o4.w);
    *(float4*)&g_H0A[(size_t)node * 512 + t * 4] = o4;
}

// ---------------- layer-1 aggregation, fused with edge-score dots ----------------
// Computes h1a = elu(agg + b1), then S1[node]=h1a.v1, S2[node]=h1a.v2 in-register.
__global__ void agg1_kernel(const float* __restrict__ b1, int n) {
    int w = threadIdx.x >> 5, lane = threadIdx.x & 31;
    int node = blockIdx.x * 4 + w;
    if (node >= n) return;
    int beg = g_off[node], end = g_off[node + 1];
    float adv = g_AD1[node];

    float4 acc = {0.f, 0.f, 0.f, 0.f};
    float denom = 0.f;
#pragma unroll 2
    for (int i = beg; i < end; i++) {
        int s = g_srt[i];
        float a = g_AS1[s] + adv;
        a = (a >= 0.f) ? a : 0.2f * a;
        float ex = __expf(a);
        denom += ex;
        uint2 v = *(const uint2*)&g_H1h[(size_t)s * 64 + lane * 2];
        float2 p0 = __half22float2(*reinterpret_cast<__half2*>(&v.x));
        float2 p1 = __half22float2(*reinterpret_cast<__half2*>(&v.y));
        acc.x += ex * p0.x; acc.y += ex * p0.y;
        acc.z += ex * p1.x; acc.w += ex * p1.y;
    }
    float inv = 1.f / (denom + 1e-16f);
    float4 bb = *(const float4*)&b1[lane * 4];
    float4 o4;
    o4.x = acc.x * inv + bb.x;
    o4.y = acc.y * inv + bb.y;
    o4.z = acc.z * inv + bb.z;
    o4.w = acc.w * inv + bb.w;
    o4.x = (o4.x > 0.f) ? o4.x : expm1f(o4.x);
    o4.y = (o4.y > 0.f) ? o4.y : expm1f(o4.y);
    o4.z = (o4.z > 0.f) ? o4.z : expm1f(o4.z);
    o4.w = (o4.w > 0.f) ? o4.w : expm1f(o4.w);

    // fused edge-score dots: s1 = h1a . v1, s2 = h1a . v2
    float4 v1 = *(const float4*)&g_V[lane * 4];
    float4 v2 = *(const float4*)&g_V[128 + lane * 4];
    float d1 = o4.x * v1.x + o4.y * v1.y + o4.z * v1.z + o4.w * v1.w;
    float d2 = o4.x * v2.x + o4.y * v2.y + o4.z * v2.z + o4.w * v2.w;
#pragma unroll
    for (int o = 16; o; o >>= 1) {
        d1 += __shfl_xor_sync(~0u, d1, o);
        d2 += __shfl_xor_sync(~0u, d2, o);
    }
    if (lane == 0) {
        g_S1[node] = d1;
        g_S2[node] = d2;
    }
}

// ---------------- final outer sum: out[i*n+j] = s1[i] + s2[j] + c + bedge ----------------
__global__ void outer_kernel(const float* __restrict__ bedge, float* __restrict__ out, int n) {
    int i = blockIdx.x;
    float v = g_S1[i] + bedge[0] + g_V[256];
    float* row = out + (size_t)i * n;
    int n4 = n >> 2;
    const float4* s24 = (const float4*)g_S2;
    for (int j = threadIdx.x; j < n4; j += blockDim.x) {
        float4 b = s24[j];
        float4 o = {v + b.x, v + b.y, v + b.z, v + b.w};
        __stcs(&((float4*)row)[j], o);
    }
    for (int j = (n4 << 2) + threadIdx.x; j < n; j += blockDim.x)
        row[j] = v + g_S2[j];
}

// ---------------- host launcher ----------------
extern "C" void kernel_launch(void* const* d_in, const int* in_sizes, int n_in,
                              void* d_out, int out_size) {
    const float* x        = (const float*)d_in[0];
    const int*   ei       = (const int*)d_in[1];     // int32
    const float* W0       = (const float*)d_in[2];
    const float* att_src0 = (const float*)d_in[3];
    const float* att_dst0 = (const float*)d_in[4];
    const float* b0       = (const float*)d_in[5];
    const float* W1       = (const float*)d_in[6];
    const float* att_src1 = (const float*)d_in[7];
    const float* att_dst1 = (const float*)d_in[8];
    const float* b1       = (const float*)d_in[9];
    const float* Wout     = (const float*)d_in[10];
    const float* bout     = (const float*)d_in[11];
    const float* Wedge    = (const float*)d_in[12];
    const float* bedge    = (const float*)d_in[13];
    float* out = (float*)d_out;

    int n = in_sizes[0] / 128;
    int E = in_sizes[1] / 2;
    int M = E + n;

    cudaFuncSetAttribute(gemm_tc_kernel,
                         cudaFuncAttributeMaxDynamicSharedMemorySize, GSMEM_BYTES);

    // Side stream: CSR chain feeds agg0 (evJoin right after scatter);
    // vec_kernel joins before agg1 (its consumer via the fused dot).
    cudaStream_t side;
    cudaStreamCreateWithFlags(&side, cudaStreamNonBlocking);
    cudaEvent_t evFork, evJoin, evJoin2;
    cudaEventCreateWithFlags(&evFork, cudaEventDisableTiming);
    cudaEventCreateWithFlags(&evJoin, cudaEventDisableTiming);
    cudaEventCreateWithFlags(&evJoin2, cudaEventDisableTiming);

    cudaEventRecord(evFork, (cudaStream_t)0);
    cudaStreamWaitEvent(side, evFork, 0);

    zero_deg_kernel<<<(n + 255) / 256, 256, 0, side>>>(n);
    hist_kernel<<<(M + 255) / 256, 256, 0, side>>>(ei, E, n);
    scan_kernel<<<1, 1024, 0, side>>>(n);
    scatter_kernel<<<(M + 255) / 256, 256, 0, side>>>(ei, E, n);
    cudaEventRecord(evJoin, side);
    vec_kernel<<<1, 128, 0, side>>>(Wout, bout, Wedge);
    cudaEventRecord(evJoin2, side);

    // ---- layer 0: H0 = x @ W0^T (bf16x3 TC, pipelined; also writes fp16 copy) ----
    {
        dim3 grid(512 / TBN, (n + TBM - 1) / TBM);
        gemm_tc_kernel<<<grid, 256, GSMEM_BYTES>>>(x, B_EXT, W0, nullptr, B_H0, H_H0h, n, 512, 128);
    }
    attn_coef_kernel<<<n, 128>>>(B_H0, att_src0, att_dst0, B_AS0, B_AD0, 4);

    cudaStreamWaitEvent((cudaStream_t)0, evJoin, 0);
    agg0_kernel<<<n, 128>>>(b0);

    // ---- layer 1: H1 = H0A @ W1^T (also writes fp16 copy) ----
    {
        dim3 grid(128 / TBN, (n + TBM - 1) / TBM);
        gemm_tc_kernel<<<grid, 256, GSMEM_BYTES>>>(nullptr, B_H0A, W1, nullptr, B_H1, H_H1h, n, 128, 512);
    }
    attn_coef_kernel<<<n, 128>>>(B_H1, att_src1, att_dst1, B_AS1, B_AD1, 1);

    // agg1 consumes g_V (fused edge-score dots) -> join vec first
    cudaStreamWaitEvent((cudaStream_t)0, evJoin2, 0);
    agg1_kernel<<<(n + 3) / 4, 128>>>(b1, n);

    // ---- final n x n outer sum ----
    outer_kernel<<<n, 512>>>(bedge, out, n);
}

// round 15
// speedup vs baseline: 1.0677x; 1.0672x over previous
#include <cuda_runtime.h>
#include <cuda_bf16.h>
#include <cuda_fp16.h>
#include <math.h>

// ---------------- problem constants ----------------
#define NMAX 10000
#define EMAX 320000
#define MMAX (EMAX + NMAX)   // edges + self loops

// ---------------- device scratch ----------------
__device__ __align__(16) float g_H0A[NMAX * 512];       // elu(agg0+b0), fp32 (GEMM1 A input)
__device__ __align__(16) float g_AS0[NMAX * 4];
__device__ __align__(16) float g_AD0[NMAX * 4];
__device__ __align__(16) float g_AS1[NMAX];
__device__ __align__(16) float g_AD1[NMAX];
__device__ __align__(16) float g_S1 [NMAX];
__device__ __align__(16) float g_S2 [NMAX];
__device__ __align__(16) float g_V  [260];              // v1[128], v2[128], c
__device__ __align__(16) unsigned g_H0h[NMAX * 256];    // H0 as packed half2
__device__ __align__(16) unsigned g_H1h[NMAX * 64];     // H1 as packed half2
__device__ __align__(16) int   g_deg[NMAX];
__device__ __align__(16) int   g_off[NMAX + 1];
__device__ __align__(16) int   g_cur[NMAX];
__device__ __align__(16) int   g_srt[MMAX];

// buffer ids (fp32)
#define B_H0A  1
#define B_AS0  5
#define B_AD0  6
#define B_AS1  7
#define B_AD1  8
#define B_EXT  (-1)

// half-copy ids
#define H_H0h  0
#define H_H1h  1

__device__ __forceinline__ float* buf_sel(int id) {
    switch (id) {
        case B_H0A: return g_H0A;
        case B_AS0: return g_AS0;
        case B_AD0: return g_AD0;
        case B_AS1: return g_AS1;
        default:    return g_AD1;
    }
}

__device__ __forceinline__ unsigned* hbuf_sel(int id) {
    return (id == H_H0h) ? g_H0h : g_H1h;
}

// ---------------- CSR build kernels ----------------
__global__ void zero_deg_kernel(int n) {
    int i = blockIdx.x * blockDim.x + threadIdx.x;
    if (i < n) g_deg[i] = 0;
}

// zero the attention accumulators (AS0/AD0/AS1/AD1) on the main stream
__global__ void zero_attn_kernel(int n) {
    int i = blockIdx.x * blockDim.x + threadIdx.x;
    if (i < n * 4) { g_AS0[i] = 0.f; g_AD0[i] = 0.f; }
    if (i < n)     { g_AS1[i] = 0.f; g_AD1[i] = 0.f; }
}

__global__ void hist_kernel(const int* __restrict__ ei, int E, int n) {
    int e = blockIdx.x * blockDim.x + threadIdx.x;
    int M = E + n;
    if (e >= M) return;
    int dst = (e < E) ? ei[E + e] : (e - E);
    if ((unsigned)dst < (unsigned)n)
        atomicAdd(&g_deg[dst], 1);
}

__global__ void scan_kernel(int n) {
    __shared__ int sm[1024];
    int t = threadIdx.x;
    int chunk = (n + 1023) >> 10;
    int b = t * chunk;
    int e = min(n, b + chunk);
    int s = 0;
    for (int i = b; i < e; i++) s += g_deg[i];
    sm[t] = s;
    __syncthreads();
    for (int o = 1; o < 1024; o <<= 1) {
        int v = (t >= o) ? sm[t - o] : 0;
        __syncthreads();
        sm[t] += v;
        __syncthreads();
    }
    int run = sm[t] - s;
    for (int i = b; i < e; i++) {
        g_off[i] = run;
        g_cur[i] = run;
        run += g_deg[i];
    }
    if (t == 1023) g_off[n] = sm[1023];
}

__global__ void scatter_kernel(const int* __restrict__ ei, int E, int n) {
    int e = blockIdx.x * blockDim.x + threadIdx.x;
    int M = E + n;
    if (e >= M) return;
    int src, dst;
    if (e < E) { src = ei[e]; dst = ei[E + e]; }
    else       { src = e - E; dst = e - E; }
    if ((unsigned)dst >= (unsigned)n || (unsigned)src >= (unsigned)n) return;
    int pos = atomicAdd(&g_cur[dst], 1);
    if (pos < MMAX) g_srt[pos] = src;
}

// ---------------- v-vectors: v1 = Wout^T w1, v2 = Wout^T w2, c = bout.(w1+w2) ----------------
__global__ void vec_kernel(const float* __restrict__ Wout, const float* __restrict__ bout,
                           const float* __restrict__ Wedge) {
    int k = threadIdx.x;   // 128
    float a1 = 0.f, a2 = 0.f;
    for (int j = 0; j < 128; j++) {
        float wo = Wout[j * 128 + k];
        a1 += wo * Wedge[j];
        a2 += wo * Wedge[128 + j];
    }
    g_V[k] = a1;
    g_V[128 + k] = a2;
    if (k == 0) {
        float c = 0.f;
        for (int j = 0; j < 128; j++) c += bout[j] * (Wedge[j] + Wedge[128 + j]);
        g_V[256] = c;
    }
}

// ---------------- bf16x3 TC GEMM, pipelined, fused attention epilogue ----------------
// C[M,N] = A[M,K]*B[N,K]^T. Outputs: packed half2 copy (always) and fused
// attention coefficients AS[row*heads+head] += sum_c C[row,c]*atts[head,c%128]
// (likewise AD) via quad-reduced atomicAdd. fp32 C is NOT written (dead).
#define TBM 128
#define TBN 64
#define TBK 32
#define KP  (TBK / 2)
#define SSTR (KP + 4)     // 20
#define A_SZ (TBM * SSTR)
#define B_SZ (TBN * SSTR)
#define GSMEM_BYTES (2 * (A_SZ + A_SZ + B_SZ + B_SZ) * 4)  // 61440

__device__ __forceinline__ unsigned pack_bf2(float a, float b) {
    __nv_bfloat162 p = __floats2bfloat162_rn(a, b);
    return *reinterpret_cast<unsigned*>(&p);
}

__device__ __forceinline__ void mma_bf16(float acc[4], unsigned a0, unsigned a1,
                                         unsigned a2, unsigned a3,
                                         unsigned b0, unsigned b1) {
    asm volatile(
        "mma.sync.aligned.m16n8k16.row.col.f32.bf16.bf16.f32 "
        "{%0,%1,%2,%3}, {%4,%5,%6,%7}, {%8,%9}, {%0,%1,%2,%3};"
        : "+f"(acc[0]), "+f"(acc[1]), "+f"(acc[2]), "+f"(acc[3])
        : "r"(a0), "r"(a1), "r"(a2), "r"(a3), "r"(b0), "r"(b1));
}

__global__ void __launch_bounds__(256)
gemm_tc_kernel(const float* __restrict__ Aext, int aid,
               const float* __restrict__ B,
               int c2id,
               const float* __restrict__ atts, const float* __restrict__ attd,
               int asid, int adid, int heads,
               int M, int N, int K) {
    const float* A = (aid == B_EXT) ? Aext : buf_sel(aid);
    unsigned* C2 = hbuf_sel(c2id);
    float* AS = buf_sel(asid);
    float* AD = buf_sel(adid);
    int N2 = N >> 1;

    extern __shared__ unsigned smu[];
    unsigned* AsH = smu;
    unsigned* AsL = AsH + 2 * A_SZ;
    unsigned* BsH = AsL + 2 * A_SZ;
    unsigned* BsL = BsH + 2 * B_SZ;

    int tid = threadIdx.x;
    int warp = tid >> 5, lane = tid & 31;
    int wm = warp >> 2;
    int wn = warp & 3;
    int bm = blockIdx.y * TBM;
    int bn = blockIdx.x * TBN;

    int lr = tid >> 3;
    int lc = tid & 7;

    float acc[4][2][4];
#pragma unroll
    for (int mt = 0; mt < 4; mt++)
#pragma unroll
        for (int nt = 0; nt < 2; nt++)
#pragma unroll
            for (int r = 0; r < 4; r++) acc[mt][nt][r] = 0.f;

    int qrow = lane >> 2;
    int qcol = lane & 3;

    float4 ra[4], rb[2];

    auto load_tile = [&](int k0) {
#pragma unroll
        for (int i = 0; i < 4; i++) {
            int rg = bm + lr + 32 * i;
            ra[i] = make_float4(0.f, 0.f, 0.f, 0.f);
            if (rg < M) ra[i] = *(const float4*)&A[(size_t)rg * K + k0 + lc * 4];
        }
#pragma unroll
        for (int i = 0; i < 2; i++)
            rb[i] = *(const float4*)&B[(size_t)(bn + lr + 32 * i) * K + k0 + lc * 4];
    };

    auto cvt_store = [&](int buf) {
        unsigned* aH = AsH + buf * A_SZ;
        unsigned* aL = AsL + buf * A_SZ;
        unsigned* bH = BsH + buf * B_SZ;
        unsigned* bL = BsL + buf * B_SZ;
#pragma unroll
        for (int i = 0; i < 4; i++) {
            float4 v = ra[i];
            float hx = __bfloat162float(__float2bfloat16_rn(v.x));
            float hy = __bfloat162float(__float2bfloat16_rn(v.y));
            float hz = __bfloat162float(__float2bfloat16_rn(v.z));
            float hw = __bfloat162float(__float2bfloat16_rn(v.w));
            int rl = lr + 32 * i;
            unsigned* dH = &aH[rl * SSTR + lc * 2];
            unsigned* dL = &aL[rl * SSTR + lc * 2];
            dH[0] = pack_bf2(hx, hy);
            dH[1] = pack_bf2(hz, hw);
            dL[0] = pack_bf2(v.x - hx, v.y - hy);
            dL[1] = pack_bf2(v.z - hz, v.w - hw);
        }
#pragma unroll
        for (int i = 0; i < 2; i++) {
            float4 v = rb[i];
            float hx = __bfloat162float(__float2bfloat16_rn(v.x));
            float hy = __bfloat162float(__float2bfloat16_rn(v.y));
            float hz = __bfloat162float(__float2bfloat16_rn(v.z));
            float hw = __bfloat162float(__float2bfloat16_rn(v.w));
            int rl = lr + 32 * i;
            unsigned* dH = &bH[rl * SSTR + lc * 2];
            unsigned* dL = &bL[rl * SSTR + lc * 2];
            dH[0] = pack_bf2(hx, hy);
            dH[1] = pack_bf2(hz, hw);
            dL[0] = pack_bf2(v.x - hx, v.y - hy);
            dL[1] = pack_bf2(v.z - hz, v.w - hw);
        }
    };

    int nTiles = K / TBK;

    load_tile(0);
    cvt_store(0);
    __syncthreads();

    for (int kt = 0; kt < nTiles; kt++) {
        int cur = kt & 1;
        if (kt + 1 < nTiles) load_tile((kt + 1) * TBK);

        unsigned* aH = AsH + cur * A_SZ;
        unsigned* aL = AsL + cur * A_SZ;
        unsigned* bH = BsH + cur * B_SZ;
        unsigned* bL = BsL + cur * B_SZ;

#pragma unroll
        for (int ks = 0; ks < TBK / 16; ks++) {
            int kb = ks * 8;
            unsigned bh[2][2], bl[2][2];
#pragma unroll
            for (int nt = 0; nt < 2; nt++) {
                int nn = wn * 16 + nt * 8 + qrow;
                bh[nt][0] = bH[nn * SSTR + kb + qcol];
                bh[nt][1] = bH[nn * SSTR + kb + qcol + 4];
                bl[nt][0] = bL[nn * SSTR + kb + qcol];
                bl[nt][1] = bL[nn * SSTR + kb + qcol + 4];
            }
#pragma unroll
            for (int mt = 0; mt < 4; mt++) {
                int mm = wm * 64 + mt * 16 + qrow;
                unsigned ah0 = aH[mm * SSTR + kb + qcol];
                unsigned ah1 = aH[(mm + 8) * SSTR + kb + qcol];
                unsigned ah2 = aH[mm * SSTR + kb + qcol + 4];
                unsigned ah3 = aH[(mm + 8) * SSTR + kb + qcol + 4];
                unsigned al0 = aL[mm * SSTR + kb + qcol];
                unsigned al1 = aL[(mm + 8) * SSTR + kb + qcol];
                unsigned al2 = aL[mm * SSTR + kb + qcol + 4];
                unsigned al3 = aL[(mm + 8) * SSTR + kb + qcol + 4];
#pragma unroll
                for (int nt = 0; nt < 2; nt++) {
                    mma_bf16(acc[mt][nt], ah0, ah1, ah2, ah3, bh[nt][0], bh[nt][1]);
                    mma_bf16(acc[mt][nt], ah0, ah1, ah2, ah3, bl[nt][0], bl[nt][1]);
                    mma_bf16(acc[mt][nt], al0, al1, al2, al3, bh[nt][0], bh[nt][1]);
                }
            }
        }

        if (kt + 1 < nTiles) cvt_store((kt + 1) & 1);
        __syncthreads();
    }

    // ---- epilogue 1: packed-half C2 writes ----
#pragma unroll
    for (int mt = 0; mt < 4; mt++) {
#pragma unroll
        for (int nt = 0; nt < 2; nt++) {
            int row = bm + wm * 64 + mt * 16 + qrow;
            int col = bn + wn * 16 + nt * 8 + qcol * 2;
            if (row < M) {
                __half2 h = __floats2half2_rn(acc[mt][nt][0], acc[mt][nt][1]);
                C2[(size_t)row * N2 + (col >> 1)] = *reinterpret_cast<unsigned*>(&h);
            }
            if (row + 8 < M) {
                __half2 h = __floats2half2_rn(acc[mt][nt][2], acc[mt][nt][3]);
                C2[(size_t)(row + 8) * N2 + (col >> 1)] = *reinterpret_cast<unsigned*>(&h);
            }
        }
    }

    // ---- epilogue 2: fused attention coefficients ----
    // warp covers 16 cols [bn+wn*16, +16), entirely inside one 128-wide head
    {
        int colbase = bn + wn * 16;
        int head = colbase >> 7;
        // att values for this thread's 4 columns (independent of mt)
        float as_[2][2], ad_[2][2];
#pragma unroll
        for (int nt = 0; nt < 2; nt++) {
            int cm = (colbase + nt * 8 + qcol * 2) & 127;
            as_[nt][0] = atts[head * 128 + cm];
            as_[nt][1] = atts[head * 128 + cm + 1];
            ad_[nt][0] = attd[head * 128 + cm];
            ad_[nt][1] = attd[head * 128 + cm + 1];
        }
#pragma unroll
        for (int mt = 0; mt < 4; mt++) {
            float s0 = 0.f, d0 = 0.f, s8 = 0.f, d8 = 0.f;
#pragma unroll
            for (int nt = 0; nt < 2; nt++) {
                s0 += acc[mt][nt][0] * as_[nt][0] + acc[mt][nt][1] * as_[nt][1];
                d0 += acc[mt][nt][0] * ad_[nt][0] + acc[mt][nt][1] * ad_[nt][1];
                s8 += acc[mt][nt][2] * as_[nt][0] + acc[mt][nt][3] * as_[nt][1];
                d8 += acc[mt][nt][2] * ad_[nt][0] + acc[mt][nt][3] * ad_[nt][1];
            }
            // reduce over the 4 qcol lanes (lane bits 0..1)
#pragma unroll
            for (int o = 1; o <= 2; o <<= 1) {
                s0 += __shfl_xor_sync(~0u, s0, o);
                d0 += __shfl_xor_sync(~0u, d0, o);
                s8 += __shfl_xor_sync(~0u, s8, o);
                d8 += __shfl_xor_sync(~0u, d8, o);
            }
            if (qcol == 0) {
                int row = bm + wm * 64 + mt * 16 + qrow;
                if (row < M) {
                    atomicAdd(&AS[row * heads + head], s0);
                    atomicAdd(&AD[row * heads + head], d0);
                }
                if (row + 8 < M) {
                    atomicAdd(&AS[(row + 8) * heads + head], s8);
                    atomicAdd(&AD[(row + 8) * heads + head], d8);
                }
            }
        }
    }
}

// ---------------- layer-0 aggregation: fp16 gather ----------------
__global__ void agg0_kernel(const float* __restrict__ b0) {
    int node = blockIdx.x;
    int t = threadIdx.x;            // 128
    int w = t >> 5;
    int beg = g_off[node], end = g_off[node + 1];

    float adsth = g_AD0[node * 4 + w];

    float4 acc = {0.f, 0.f, 0.f, 0.f};
    float denom = 0.f;
#pragma unroll 2
    for (int i = beg; i < end; i++) {
        int s = g_srt[i];
        float a = g_AS0[s * 4 + w] + adsth;
        a = (a >= 0.f) ? a : 0.2f * a;
        float ex = __expf(a);
        denom += ex;
        uint2 v = *(const uint2*)&g_H0h[(size_t)s * 256 + t * 2];
        float2 p0 = __half22float2(*reinterpret_cast<__half2*>(&v.x));
        float2 p1 = __half22float2(*reinterpret_cast<__half2*>(&v.y));
        acc.x += ex * p0.x; acc.y += ex * p0.y;
        acc.z += ex * p1.x; acc.w += ex * p1.y;
    }
    float inv = 1.f / (denom + 1e-16f);
    float4 bb = *(const float4*)&b0[t * 4];
    float4 o4;
    o4.x = acc.x * inv + bb.x;
    o4.y = acc.y * inv + bb.y;
    o4.z = acc.z * inv + bb.z;
    o4.w = acc.w * inv + bb.w;
    o4.x = (o4.x > 0.f) ? o4.x : expm1f(o4.x);
    o4.y = (o4.y > 0.f) ? o4.y : expm1f(o4.y);
    o4.z = (o4.z > 0.f) ? o4.z : expm1f(o4.z);
    o4.w = (o4.w > 0.f) ? o4.w : expm1f(o4.w);
    *(float4*)&g_H0A[(size_t)node * 512 + t * 4] = o4;
}

// ---------------- layer-1 aggregation, fused with edge-score dots ----------------
__global__ void agg1_kernel(const float* __restrict__ b1, int n) {
    int w = threadIdx.x >> 5, lane = threadIdx.x & 31;
    int node = blockIdx.x * 4 + w;
    if (node >= n) return;
    int beg = g_off[node], end = g_off[node + 1];
    float adv = g_AD1[node];

    float4 acc = {0.f, 0.f, 0.f, 0.f};
    float denom = 0.f;
#pragma unroll 2
    for (int i = beg; i < end; i++) {
        int s = g_srt[i];
        float a = g_AS1[s] + adv;
        a = (a >= 0.f) ? a : 0.2f * a;
        float ex = __expf(a);
        denom += ex;
        uint2 v = *(const uint2*)&g_H1h[(size_t)s * 64 + lane * 2];
        float2 p0 = __half22float2(*reinterpret_cast<__half2*>(&v.x));
        float2 p1 = __half22float2(*reinterpret_cast<__half2*>(&v.y));
        acc.x += ex * p0.x; acc.y += ex * p0.y;
        acc.z += ex * p1.x; acc.w += ex * p1.y;
    }
    float inv = 1.f / (denom + 1e-16f);
    float4 bb = *(const float4*)&b1[lane * 4];
    float4 o4;
    o4.x = acc.x * inv + bb.x;
    o4.y = acc.y * inv + bb.y;
    o4.z = acc.z * inv + bb.z;
    o4.w = acc.w * inv + bb.w;
    o4.x = (o4.x > 0.f) ? o4.x : expm1f(o4.x);
    o4.y = (o4.y > 0.f) ? o4.y : expm1f(o4.y);
    o4.z = (o4.z > 0.f) ? o4.z : expm1f(o4.z);
    o4.w = (o4.w > 0.f) ? o4.w : expm1f(o4.w);

    // fused edge-score dots: s1 = h1a . v1, s2 = h1a . v2
    float4 v1 = *(const float4*)&g_V[lane * 4];
    float4 v2 = *(const float4*)&g_V[128 + lane * 4];
    float d1 = o4.x * v1.x + o4.y * v1.y + o4.z * v1.z + o4.w * v1.w;
    float d2 = o4.x * v2.x + o4.y * v2.y + o4.z * v2.z + o4.w * v2.w;
#pragma unroll
    for (int o = 16; o; o >>= 1) {
        d1 += __shfl_xor_sync(~0u, d1, o);
        d2 += __shfl_xor_sync(~0u, d2, o);
    }
    if (lane == 0) {
        g_S1[node] = d1;
        g_S2[node] = d2;
    }
}

// ---------------- final outer sum: out[i*n+j] = s1[i] + s2[j] + c + bedge ----------------
__global__ void outer_kernel(const float* __restrict__ bedge, float* __restrict__ out, int n) {
    int i = blockIdx.x;
    float v = g_S1[i] + bedge[0] + g_V[256];
    float* row = out + (size_t)i * n;
    int n4 = n >> 2;
    const float4* s24 = (const float4*)g_S2;
    for (int j = threadIdx.x; j < n4; j += blockDim.x) {
        float4 b = s24[j];
        float4 o = {v + b.x, v + b.y, v + b.z, v + b.w};
        __stcs(&((float4*)row)[j], o);
    }
    for (int j = (n4 << 2) + threadIdx.x; j < n; j += blockDim.x)
        row[j] = v + g_S2[j];
}

// ---------------- host launcher ----------------
extern "C" void kernel_launch(void* const* d_in, const int* in_sizes, int n_in,
                              void* d_out, int out_size) {
    const float* x        = (const float*)d_in[0];
    const int*   ei       = (const int*)d_in[1];     // int32
    const float* W0       = (const float*)d_in[2];
    const float* att_src0 = (const float*)d_in[3];
    const float* att_dst0 = (const float*)d_in[4];
    const float* b0       = (const float*)d_in[5];
    const float* W1       = (const float*)d_in[6];
    const float* att_src1 = (const float*)d_in[7];
    const float* att_dst1 = (const float*)d_in[8];
    const float* b1       = (const float*)d_in[9];
    const float* Wout     = (const float*)d_in[10];
    const float* bout     = (const float*)d_in[11];
    const float* Wedge    = (const float*)d_in[12];
    const float* bedge    = (const float*)d_in[13];
    float* out = (float*)d_out;

    int n = in_sizes[0] / 128;
    int E = in_sizes[1] / 2;
    int M = E + n;

    cudaFuncSetAttribute(gemm_tc_kernel,
                         cudaFuncAttributeMaxDynamicSharedMemorySize, GSMEM_BYTES);

    // Side stream: CSR chain feeds agg0 (evJoin right after scatter);
    // vec_kernel joins before agg1 (fused dot consumer).
    cudaStream_t side;
    cudaStreamCreateWithFlags(&side, cudaStreamNonBlocking);
    cudaEvent_t evFork, evJoin, evJoin2;
    cudaEventCreateWithFlags(&evFork, cudaEventDisableTiming);
    cudaEventCreateWithFlags(&evJoin, cudaEventDisableTiming);
    cudaEventCreateWithFlags(&evJoin2, cudaEventDisableTiming);

    cudaEventRecord(evFork, (cudaStream_t)0);
    cudaStreamWaitEvent(side, evFork, 0);

    zero_deg_kernel<<<(n + 255) / 256, 256, 0, side>>>(n);
    hist_kernel<<<(M + 255) / 256, 256, 0, side>>>(ei, E, n);
    scan_kernel<<<1, 1024, 0, side>>>(n);
    scatter_kernel<<<(M + 255) / 256, 256, 0, side>>>(ei, E, n);
    cudaEventRecord(evJoin, side);
    vec_kernel<<<1, 128, 0, side>>>(Wout, bout, Wedge);
    cudaEventRecord(evJoin2, side);

    // zero attention accumulators (main stream, before GEMM0's fused atomics)
    zero_attn_kernel<<<(n * 4 + 255) / 256, 256>>>(n);

    // ---- layer 0: H0 = x @ W0^T (bf16x3 TC; writes fp16 copy + fused attn0) ----
    {
        dim3 grid(512 / TBN, (n + TBM - 1) / TBM);
        gemm_tc_kernel<<<grid, 256, GSMEM_BYTES>>>(
            x, B_EXT, W0, H_H0h,
            att_src0, att_dst0, B_AS0, B_AD0, 4,
            n, 512, 128);
    }

    cudaStreamWaitEvent((cudaStream_t)0, evJoin, 0);
    agg0_kernel<<<n, 128>>>(b0);

    // ---- layer 1: H1 = H0A @ W1^T (writes fp16 copy + fused attn1) ----
    {
        dim3 grid(128 / TBN, (n + TBM - 1) / TBM);
        gemm_tc_kernel<<<grid, 256, GSMEM_BYTES>>>(
            nullptr, B_H0A, W1, H_H1h,
            att_src1, att_dst1, B_AS1, B_AD1, 1,
            n, 128, 512);
    }

    // agg1 consumes g_V (fused edge-score dots) -> join vec first
    cudaStreamWaitEvent((cudaStream_t)0, evJoin2, 0);
    agg1_kernel<<<(n + 3) / 4, 128>>>(b1, n);

    // ---- final n x n outer sum ----
    outer_kernel<<<n, 512>>>(bedge, out, n);
}

// round 16
// speedup vs baseline: 1.0885x; 1.0194x over previous
#include <cuda_runtime.h>
#include <cuda_bf16.h>
#include <cuda_fp16.h>
#include <math.h>

// ---------------- problem constants ----------------
#define NMAX 10000
#define EMAX 320000
#define MMAX (EMAX + NMAX)   // edges + self loops

// ---------------- device scratch ----------------
__device__ __align__(16) float g_H0A[NMAX * 512];       // elu(agg0+b0), fp32 (GEMM1 A input)
__device__ __align__(16) float g_AS0[NMAX * 4];
__device__ __align__(16) float g_AD0[NMAX * 4];
__device__ __align__(16) float g_AS1[NMAX];
__device__ __align__(16) float g_AD1[NMAX];
__device__ __align__(16) float g_S1 [NMAX];
__device__ __align__(16) float g_S2 [NMAX];
__device__ __align__(16) float g_V  [260];              // v1[128], v2[128], c
__device__ __align__(16) unsigned g_H0h[NMAX * 256];    // H0 as packed half2
__device__ __align__(16) unsigned g_H1h[NMAX * 64];     // H1 as packed half2
__device__ __align__(16) int   g_deg[NMAX];
__device__ __align__(16) int   g_off[NMAX + 1];
__device__ __align__(16) int   g_cur[NMAX];
__device__ __align__(16) int   g_srt[MMAX];

// buffer ids (fp32)
#define B_H0A  1
#define B_AS0  5
#define B_AD0  6
#define B_AS1  7
#define B_AD1  8
#define B_EXT  (-1)

// half-copy ids
#define H_H0h  0
#define H_H1h  1

__device__ __forceinline__ float* buf_sel(int id) {
    switch (id) {
        case B_H0A: return g_H0A;
        case B_AS0: return g_AS0;
        case B_AD0: return g_AD0;
        case B_AS1: return g_AS1;
        default:    return g_AD1;
    }
}

__device__ __forceinline__ unsigned* hbuf_sel(int id) {
    return (id == H_H0h) ? g_H0h : g_H1h;
}

// ---------------- CSR build kernels ----------------
__global__ void zero_deg_kernel(int n) {
    int i = blockIdx.x * blockDim.x + threadIdx.x;
    if (i < n) g_deg[i] = 0;
}

// zero the attention accumulators (AS0/AD0/AS1/AD1)
__global__ void zero_attn_kernel(int n) {
    int i = blockIdx.x * blockDim.x + threadIdx.x;
    if (i < n * 4) { g_AS0[i] = 0.f; g_AD0[i] = 0.f; }
    if (i < n)     { g_AS1[i] = 0.f; g_AD1[i] = 0.f; }
}

__global__ void hist_kernel(const int* __restrict__ ei, int E, int n) {
    int e = blockIdx.x * blockDim.x + threadIdx.x;
    int M = E + n;
    if (e >= M) return;
    int dst = (e < E) ? ei[E + e] : (e - E);
    if ((unsigned)dst < (unsigned)n)
        atomicAdd(&g_deg[dst], 1);
}

__global__ void scan_kernel(int n) {
    __shared__ int sm[1024];
    int t = threadIdx.x;
    int chunk = (n + 1023) >> 10;
    int b = t * chunk;
    int e = min(n, b + chunk);
    int s = 0;
    for (int i = b; i < e; i++) s += g_deg[i];
    sm[t] = s;
    __syncthreads();
    for (int o = 1; o < 1024; o <<= 1) {
        int v = (t >= o) ? sm[t - o] : 0;
        __syncthreads();
        sm[t] += v;
        __syncthreads();
    }
    int run = sm[t] - s;
    for (int i = b; i < e; i++) {
        g_off[i] = run;
        g_cur[i] = run;
        run += g_deg[i];
    }
    if (t == 1023) g_off[n] = sm[1023];
}

__global__ void scatter_kernel(const int* __restrict__ ei, int E, int n) {
    int e = blockIdx.x * blockDim.x + threadIdx.x;
    int M = E + n;
    if (e >= M) return;
    int src, dst;
    if (e < E) { src = ei[e]; dst = ei[E + e]; }
    else       { src = e - E; dst = e - E; }
    if ((unsigned)dst >= (unsigned)n || (unsigned)src >= (unsigned)n) return;
    int pos = atomicAdd(&g_cur[dst], 1);
    if (pos < MMAX) g_srt[pos] = src;
}

// ---------------- v-vectors: v1 = Wout^T w1, v2 = Wout^T w2, c = bout.(w1+w2) ----------------
__global__ void vec_kernel(const float* __restrict__ Wout, const float* __restrict__ bout,
                           const float* __restrict__ Wedge) {
    int k = threadIdx.x;   // 128
    float a1 = 0.f, a2 = 0.f;
    for (int j = 0; j < 128; j++) {
        float wo = Wout[j * 128 + k];
        a1 += wo * Wedge[j];
        a2 += wo * Wedge[128 + j];
    }
    g_V[k] = a1;
    g_V[128 + k] = a2;
    if (k == 0) {
        float c = 0.f;
        for (int j = 0; j < 128; j++) c += bout[j] * (Wedge[j] + Wedge[128 + j]);
        g_V[256] = c;
    }
}

// ---------------- bf16x3 TC GEMM, pipelined, fused attention epilogue ----------------
#define TBM 128
#define TBN 64
#define TBK 32
#define KP  (TBK / 2)
#define SSTR (KP + 4)     // 20
#define A_SZ (TBM * SSTR)
#define B_SZ (TBN * SSTR)
#define GSMEM_BYTES (2 * (A_SZ + A_SZ + B_SZ + B_SZ) * 4)  // 61440

__device__ __forceinline__ unsigned pack_bf2(float a, float b) {
    __nv_bfloat162 p = __floats2bfloat162_rn(a, b);
    return *reinterpret_cast<unsigned*>(&p);
}

__device__ __forceinline__ void mma_bf16(float acc[4], unsigned a0, unsigned a1,
                                         unsigned a2, unsigned a3,
                                         unsigned b0, unsigned b1) {
    asm volatile(
        "mma.sync.aligned.m16n8k16.row.col.f32.bf16.bf16.f32 "
        "{%0,%1,%2,%3}, {%4,%5,%6,%7}, {%8,%9}, {%0,%1,%2,%3};"
        : "+f"(acc[0]), "+f"(acc[1]), "+f"(acc[2]), "+f"(acc[3])
        : "r"(a0), "r"(a1), "r"(a2), "r"(a3), "r"(b0), "r"(b1));
}

__global__ void __launch_bounds__(256)
gemm_tc_kernel(const float* __restrict__ Aext, int aid,
               const float* __restrict__ B,
               int c2id,
               const float* __restrict__ atts, const float* __restrict__ attd,
               int asid, int adid, int heads,
               int M, int N, int K) {
    const float* A = (aid == B_EXT) ? Aext : buf_sel(aid);
    unsigned* C2 = hbuf_sel(c2id);
    float* AS = buf_sel(asid);
    float* AD = buf_sel(adid);
    int N2 = N >> 1;

    extern __shared__ unsigned smu[];
    unsigned* AsH = smu;
    unsigned* AsL = AsH + 2 * A_SZ;
    unsigned* BsH = AsL + 2 * A_SZ;
    unsigned* BsL = BsH + 2 * B_SZ;

    int tid = threadIdx.x;
    int warp = tid >> 5, lane = tid & 31;
    int wm = warp >> 2;
    int wn = warp & 3;
    int bm = blockIdx.y * TBM;
    int bn = blockIdx.x * TBN;

    int lr = tid >> 3;
    int lc = tid & 7;

    float acc[4][2][4];
#pragma unroll
    for (int mt = 0; mt < 4; mt++)
#pragma unroll
        for (int nt = 0; nt < 2; nt++)
#pragma unroll
            for (int r = 0; r < 4; r++) acc[mt][nt][r] = 0.f;

    int qrow = lane >> 2;
    int qcol = lane & 3;

    float4 ra[4], rb[2];

    auto load_tile = [&](int k0) {
#pragma unroll
        for (int i = 0; i < 4; i++) {
            int rg = bm + lr + 32 * i;
            ra[i] = make_float4(0.f, 0.f, 0.f, 0.f);
            if (rg < M) ra[i] = *(const float4*)&A[(size_t)rg * K + k0 + lc * 4];
        }
#pragma unroll
        for (int i = 0; i < 2; i++)
            rb[i] = *(const float4*)&B[(size_t)(bn + lr + 32 * i) * K + k0 + lc * 4];
    };

    auto cvt_store = [&](int buf) {
        unsigned* aH = AsH + buf * A_SZ;
        unsigned* aL = AsL + buf * A_SZ;
        unsigned* bH = BsH + buf * B_SZ;
        unsigned* bL = BsL + buf * B_SZ;
#pragma unroll
        for (int i = 0; i < 4; i++) {
            float4 v = ra[i];
            float hx = __bfloat162float(__float2bfloat16_rn(v.x));
            float hy = __bfloat162float(__float2bfloat16_rn(v.y));
            float hz = __bfloat162float(__float2bfloat16_rn(v.z));
            float hw = __bfloat162float(__float2bfloat16_rn(v.w));
            int rl = lr + 32 * i;
            unsigned* dH = &aH[rl * SSTR + lc * 2];
            unsigned* dL = &aL[rl * SSTR + lc * 2];
            dH[0] = pack_bf2(hx, hy);
            dH[1] = pack_bf2(hz, hw);
            dL[0] = pack_bf2(v.x - hx, v.y - hy);
            dL[1] = pack_bf2(v.z - hz, v.w - hw);
        }
#pragma unroll
        for (int i = 0; i < 2; i++) {
            float4 v = rb[i];
            float hx = __bfloat162float(__float2bfloat16_rn(v.x));
            float hy = __bfloat162float(__float2bfloat16_rn(v.y));
            float hz = __bfloat162float(__float2bfloat16_rn(v.z));
            float hw = __bfloat162float(__float2bfloat16_rn(v.w));
            int rl = lr + 32 * i;
            unsigned* dH = &bH[rl * SSTR + lc * 2];
            unsigned* dL = &bL[rl * SSTR + lc * 2];
            dH[0] = pack_bf2(hx, hy);
            dH[1] = pack_bf2(hz, hw);
            dL[0] = pack_bf2(v.x - hx, v.y - hy);
            dL[1] = pack_bf2(v.z - hz, v.w - hw);
        }
    };

    int nTiles = K / TBK;

    load_tile(0);
    cvt_store(0);
    __syncthreads();

    for (int kt = 0; kt < nTiles; kt++) {
        int cur = kt & 1;
        if (kt + 1 < nTiles) load_tile((kt + 1) * TBK);

        unsigned* aH = AsH + cur * A_SZ;
        unsigned* aL = AsL + cur * A_SZ;
        unsigned* bH = BsH + cur * B_SZ;
        unsigned* bL = BsL + cur * B_SZ;

#pragma unroll
        for (int ks = 0; ks < TBK / 16; ks++) {
            int kb = ks * 8;
            unsigned bh[2][2], bl[2][2];
#pragma unroll
            for (int nt = 0; nt < 2; nt++) {
                int nn = wn * 16 + nt * 8 + qrow;
                bh[nt][0] = bH[nn * SSTR + kb + qcol];
                bh[nt][1] = bH[nn * SSTR + kb + qcol + 4];
                bl[nt][0] = bL[nn * SSTR + kb + qcol];
                bl[nt][1] = bL[nn * SSTR + kb + qcol + 4];
            }
#pragma unroll
            for (int mt = 0; mt < 4; mt++) {
                int mm = wm * 64 + mt * 16 + qrow;
                unsigned ah0 = aH[mm * SSTR + kb + qcol];
                unsigned ah1 = aH[(mm + 8) * SSTR + kb + qcol];
                unsigned ah2 = aH[mm * SSTR + kb + qcol + 4];
                unsigned ah3 = aH[(mm + 8) * SSTR + kb + qcol + 4];
                unsigned al0 = aL[mm * SSTR + kb + qcol];
                unsigned al1 = aL[(mm + 8) * SSTR + kb + qcol];
                unsigned al2 = aL[mm * SSTR + kb + qcol + 4];
                unsigned al3 = aL[(mm + 8) * SSTR + kb + qcol + 4];
#pragma unroll
                for (int nt = 0; nt < 2; nt++) {
                    mma_bf16(acc[mt][nt], ah0, ah1, ah2, ah3, bh[nt][0], bh[nt][1]);
                    mma_bf16(acc[mt][nt], ah0, ah1, ah2, ah3, bl[nt][0], bl[nt][1]);
                    mma_bf16(acc[mt][nt], al0, al1, al2, al3, bh[nt][0], bh[nt][1]);
                }
            }
        }

        if (kt + 1 < nTiles) cvt_store((kt + 1) & 1);
        __syncthreads();
    }

    // ---- epilogue 1: packed-half C2 writes ----
#pragma unroll
    for (int mt = 0; mt < 4; mt++) {
#pragma unroll
        for (int nt = 0; nt < 2; nt++) {
            int row = bm + wm * 64 + mt * 16 + qrow;
            int col = bn + wn * 16 + nt * 8 + qcol * 2;
            if (row < M) {
                __half2 h = __floats2half2_rn(acc[mt][nt][0], acc[mt][nt][1]);
                C2[(size_t)row * N2 + (col >> 1)] = *reinterpret_cast<unsigned*>(&h);
            }
            if (row + 8 < M) {
                __half2 h = __floats2half2_rn(acc[mt][nt][2], acc[mt][nt][3]);
                C2[(size_t)(row + 8) * N2 + (col >> 1)] = *reinterpret_cast<unsigned*>(&h);
            }
        }
    }

    // ---- epilogue 2: fused attention coefficients ----
    {
        int colbase = bn + wn * 16;
        int head = colbase >> 7;
        float as_[2][2], ad_[2][2];
#pragma unroll
        for (int nt = 0; nt < 2; nt++) {
            int cm = (colbase + nt * 8 + qcol * 2) & 127;
            as_[nt][0] = atts[head * 128 + cm];
            as_[nt][1] = atts[head * 128 + cm + 1];
            ad_[nt][0] = attd[head * 128 + cm];
            ad_[nt][1] = attd[head * 128 + cm + 1];
        }
#pragma unroll
        for (int mt = 0; mt < 4; mt++) {
            float s0 = 0.f, d0 = 0.f, s8 = 0.f, d8 = 0.f;
#pragma unroll
            for (int nt = 0; nt < 2; nt++) {
                s0 += acc[mt][nt][0] * as_[nt][0] + acc[mt][nt][1] * as_[nt][1];
                d0 += acc[mt][nt][0] * ad_[nt][0] + acc[mt][nt][1] * ad_[nt][1];
                s8 += acc[mt][nt][2] * as_[nt][0] + acc[mt][nt][3] * as_[nt][1];
                d8 += acc[mt][nt][2] * ad_[nt][0] + acc[mt][nt][3] * ad_[nt][1];
            }
#pragma unroll
            for (int o = 1; o <= 2; o <<= 1) {
                s0 += __shfl_xor_sync(~0u, s0, o);
                d0 += __shfl_xor_sync(~0u, d0, o);
                s8 += __shfl_xor_sync(~0u, s8, o);
                d8 += __shfl_xor_sync(~0u, d8, o);
            }
            if (qcol == 0) {
                int row = bm + wm * 64 + mt * 16 + qrow;
                if (row < M) {
                    atomicAdd(&AS[row * heads + head], s0);
                    atomicAdd(&AD[row * heads + head], d0);
                }
                if (row + 8 < M) {
                    atomicAdd(&AS[(row + 8) * heads + head], s8);
                    atomicAdd(&AD[(row + 8) * heads + head], d8);
                }
            }
        }
    }
}

// ---------------- layer-0 aggregation: fp16 gather ----------------
__global__ void agg0_kernel(const float* __restrict__ b0) {
    int node = blockIdx.x;
    int t = threadIdx.x;            // 128
    int w = t >> 5;
    int beg = g_off[node], end = g_off[node + 1];

    float adsth = g_AD0[node * 4 + w];

    float4 acc = {0.f, 0.f, 0.f, 0.f};
    float denom = 0.f;
#pragma unroll 4
    for (int i = beg; i < end; i++) {
        int s = g_srt[i];
        float a = g_AS0[s * 4 + w] + adsth;
        a = (a >= 0.f) ? a : 0.2f * a;
        float ex = __expf(a);
        denom += ex;
        uint2 v = *(const uint2*)&g_H0h[(size_t)s * 256 + t * 2];
        float2 p0 = __half22float2(*reinterpret_cast<__half2*>(&v.x));
        float2 p1 = __half22float2(*reinterpret_cast<__half2*>(&v.y));
        acc.x += ex * p0.x; acc.y += ex * p0.y;
        acc.z += ex * p1.x; acc.w += ex * p1.y;
    }
    float inv = 1.f / (denom + 1e-16f);
    float4 bb = *(const float4*)&b0[t * 4];
    float4 o4;
    o4.x = acc.x * inv + bb.x;
    o4.y = acc.y * inv + bb.y;
    o4.z = acc.z * inv + bb.z;
    o4.w = acc.w * inv + bb.w;
    o4.x = (o4.x > 0.f) ? o4.x : expm1f(o4.x);
    o4.y = (o4.y > 0.f) ? o4.y : expm1f(o4.y);
    o4.z = (o4.z > 0.f) ? o4.z : expm1f(o4.z);
    o4.w = (o4.w > 0.f) ? o4.w : expm1f(o4.w);
    *(float4*)&g_H0A[(size_t)node * 512 + t * 4] = o4;
}

// ---------------- layer-1 aggregation, fused with edge-score dots ----------------
__global__ void agg1_kernel(const float* __restrict__ b1, int n) {
    int w = threadIdx.x >> 5, lane = threadIdx.x & 31;
    int node = blockIdx.x * 4 + w;
    if (node >= n) return;
    int beg = g_off[node], end = g_off[node + 1];
    float adv = g_AD1[node];

    float4 acc = {0.f, 0.f, 0.f, 0.f};
    float denom = 0.f;
#pragma unroll 4
    for (int i = beg; i < end; i++) {
        int s = g_srt[i];
        float a = g_AS1[s] + adv;
        a = (a >= 0.f) ? a : 0.2f * a;
        float ex = __expf(a);
        denom += ex;
        uint2 v = *(const uint2*)&g_H1h[(size_t)s * 64 + lane * 2];
        float2 p0 = __half22float2(*reinterpret_cast<__half2*>(&v.x));
        float2 p1 = __half22float2(*reinterpret_cast<__half2*>(&v.y));
        acc.x += ex * p0.x; acc.y += ex * p0.y;
        acc.z += ex * p1.x; acc.w += ex * p1.y;
    }
    float inv = 1.f / (denom + 1e-16f);
    float4 bb = *(const float4*)&b1[lane * 4];
    float4 o4;
    o4.x = acc.x * inv + bb.x;
    o4.y = acc.y * inv + bb.y;
    o4.z = acc.z * inv + bb.z;
    o4.w = acc.w * inv + bb.w;
    o4.x = (o4.x > 0.f) ? o4.x : expm1f(o4.x);
    o4.y = (o4.y > 0.f) ? o4.y : expm1f(o4.y);
    o4.z = (o4.z > 0.f) ? o4.z : expm1f(o4.z);
    o4.w = (o4.w > 0.f) ? o4.w : expm1f(o4.w);

    float4 v1 = *(const float4*)&g_V[lane * 4];
    float4 v2 = *(const float4*)&g_V[128 + lane * 4];
    float d1 = o4.x * v1.x + o4.y * v1.y + o4.z * v1.z + o4.w * v1.w;
    float d2 = o4.x * v2.x + o4.y * v2.y + o4.z * v2.z + o4.w * v2.w;
#pragma unroll
    for (int o = 16; o; o >>= 1) {
        d1 += __shfl_xor_sync(~0u, d1, o);
        d2 += __shfl_xor_sync(~0u, d2, o);
    }
    if (lane == 0) {
        g_S1[node] = d1;
        g_S2[node] = d2;
    }
}

// ---------------- final outer sum: 8 rows/block, s2 staged in smem ----------------
#define OUT_R 8
__global__ void __launch_bounds__(512)
outer_kernel(const float* __restrict__ bedge, float* __restrict__ out, int n) {
    __shared__ float s2s[NMAX + 16];
    int t = threadIdx.x;
    int n4 = n >> 2;

    // stage s2 into smem once per block
    for (int j = t; j < n4; j += blockDim.x)
        ((float4*)s2s)[j] = ((const float4*)g_S2)[j];
    for (int j = (n4 << 2) + t; j < n; j += blockDim.x)
        s2s[j] = g_S2[j];
    __syncthreads();

    int i0 = blockIdx.x * OUT_R;
    float base = bedge[0] + g_V[256];
#pragma unroll
    for (int r = 0; r < OUT_R; r++) {
        int i = i0 + r;
        if (i >= n) break;
        float v = g_S1[i] + base;
        float* row = out + (size_t)i * n;
        for (int j = t; j < n4; j += blockDim.x) {
            float4 b = ((const float4*)s2s)[j];
            float4 o = {v + b.x, v + b.y, v + b.z, v + b.w};
            __stcs(&((float4*)row)[j], o);
        }
        for (int j = (n4 << 2) + t; j < n; j += blockDim.x)
            row[j] = v + s2s[j];
    }
}

// ---------------- host launcher ----------------
extern "C" void kernel_launch(void* const* d_in, const int* in_sizes, int n_in,
                              void* d_out, int out_size) {
    const float* x        = (const float*)d_in[0];
    const int*   ei       = (const int*)d_in[1];     // int32
    const float* W0       = (const float*)d_in[2];
    const float* att_src0 = (const float*)d_in[3];
    const float* att_dst0 = (const float*)d_in[4];
    const float* b0       = (const float*)d_in[5];
    const float* W1       = (const float*)d_in[6];
    const float* att_src1 = (const float*)d_in[7];
    const float* att_dst1 = (const float*)d_in[8];
    const float* b1       = (const float*)d_in[9];
    const float* Wout     = (const float*)d_in[10];
    const float* bout     = (const float*)d_in[11];
    const float* Wedge    = (const float*)d_in[12];
    const float* bedge    = (const float*)d_in[13];
    float* out = (float*)d_out;

    int n = in_sizes[0] / 128;
    int E = in_sizes[1] / 2;
    int M = E + n;

    cudaFuncSetAttribute(gemm_tc_kernel,
                         cudaFuncAttributeMaxDynamicSharedMemorySize, GSMEM_BYTES);

    // Side stream: zero_attn first (joins before GEMM0's fused atomics), then
    // CSR chain (joins before agg0), then vec (joins before agg1).
    cudaStream_t side;
    cudaStreamCreateWithFlags(&side, cudaStreamNonBlocking);
    cudaEvent_t evFork, evZ, evJoin, evJoin2;
    cudaEventCreateWithFlags(&evFork, cudaEventDisableTiming);
    cudaEventCreateWithFlags(&evZ, cudaEventDisableTiming);
    cudaEventCreateWithFlags(&evJoin, cudaEventDisableTiming);
    cudaEventCreateWithFlags(&evJoin2, cudaEventDisableTiming);

    cudaEventRecord(evFork, (cudaStream_t)0);
    cudaStreamWaitEvent(side, evFork, 0);

    zero_attn_kernel<<<(n * 4 + 255) / 256, 256, 0, side>>>(n);
    cudaEventRecord(evZ, side);
    zero_deg_kernel<<<(n + 255) / 256, 256, 0, side>>>(n);
    hist_kernel<<<(M + 255) / 256, 256, 0, side>>>(ei, E, n);
    scan_kernel<<<1, 1024, 0, side>>>(n);
    scatter_kernel<<<(M + 255) / 256, 256, 0, side>>>(ei, E, n);
    cudaEventRecord(evJoin, side);
    vec_kernel<<<1, 128, 0, side>>>(Wout, bout, Wedge);
    cudaEventRecord(evJoin2, side);

    // ---- layer 0: H0 = x @ W0^T (bf16x3 TC; fp16 copy + fused attn0) ----
    cudaStreamWaitEvent((cudaStream_t)0, evZ, 0);
    {
        dim3 grid(512 / TBN, (n + TBM - 1) / TBM);
        gemm_tc_kernel<<<grid, 256, GSMEM_BYTES>>>(
            x, B_EXT, W0, H_H0h,
            att_src0, att_dst0, B_AS0, B_AD0, 4,
            n, 512, 128);
    }

    cudaStreamWaitEvent((cudaStream_t)0, evJoin, 0);
    agg0_kernel<<<n, 128>>>(b0);

    // ---- layer 1: H1 = H0A @ W1^T (fp16 copy + fused attn1) ----
    {
        dim3 grid(128 / TBN, (n + TBM - 1) / TBM);
        gemm_tc_kernel<<<grid, 256, GSMEM_BYTES>>>(
            nullptr, B_H0A, W1, H_H1h,
            att_src1, att_dst1, B_AS1, B_AD1, 1,
            n, 128, 512);
    }

    // agg1 consumes g_V (fused edge-score dots) -> join vec first
    cudaStreamWaitEvent((cudaStream_t)0, evJoin2, 0);
    agg1_kernel<<<(n + 3) / 4, 128>>>(b1, n);

    // ---- final n x n outer sum (8 rows/block, smem-staged s2) ----
    outer_kernel<<<(n + OUT_R - 1) / OUT_R, 512>>>(bedge, out, n);
}